// round 1
// baseline (speedup 1.0000x reference)
#include <cuda_runtime.h>
#include <cuda_bf16.h>
#include <cstdint>

// Problem constants
#define BATCH 64
#define SEQ   197
#define DIM   768
#define HEADS 12
#define HD    64
#define M_TOT (BATCH * SEQ)      // 12608
#define QKV_N (3 * DIM)          // 2304

// Scratch (allowed: __device__ globals, no runtime allocation)
__device__ float g_qkv[(size_t)M_TOT * QKV_N];   // ~116 MB
__device__ float g_att[(size_t)M_TOT * DIM];     // ~39 MB

// ---------------------------------------------------------------------------
// SGEMM (NT): C[m,n] = sum_k A[m,k] * B[n,k]  (+ bias[n] + res[m,n] if EPI)
// A: [M,K] row-major, B: [N,K] row-major. 128x128x8 tiles, 8x8 per thread.
// N and K are multiples of 128/8 for both call sites; only M needs guarding.
// ---------------------------------------------------------------------------
template <bool EPI>
__global__ __launch_bounds__(256, 2)
void sgemm_nt(const float* __restrict__ A, const float* __restrict__ B,
              float* __restrict__ C, int M, int N, int K,
              const float* __restrict__ bias, const float* __restrict__ res)
{
    __shared__ float As[8][128];
    __shared__ float Bs[8][128];

    const int bm = blockIdx.x * 128;
    const int bn = blockIdx.y * 128;
    const int tid = threadIdx.x;

    // gmem load mapping: 128 rows x 8 k = 1024 floats -> one float4 per thread
    const int lr = tid >> 1;          // 0..127 (row within tile)
    const int lk = (tid & 1) * 4;     // 0 or 4

    const bool aval = (bm + lr) < M;
    const float* Aptr = A + (size_t)(bm + lr) * K + lk;
    const float* Bptr = B + (size_t)(bn + lr) * K + lk;

    // compute mapping: 16x16 thread grid, each thread 8x8
    const int tm = (tid >> 4) * 8;
    const int tn = (tid & 15) * 8;

    float acc[8][8];
#pragma unroll
    for (int i = 0; i < 8; i++)
#pragma unroll
        for (int j = 0; j < 8; j++) acc[i][j] = 0.f;

    for (int k0 = 0; k0 < K; k0 += 8) {
        float4 av = aval ? *(const float4*)Aptr : make_float4(0.f, 0.f, 0.f, 0.f);
        float4 bv = *(const float4*)Bptr;
        Aptr += 8; Bptr += 8;

        As[lk + 0][lr] = av.x; As[lk + 1][lr] = av.y;
        As[lk + 2][lr] = av.z; As[lk + 3][lr] = av.w;
        Bs[lk + 0][lr] = bv.x; Bs[lk + 1][lr] = bv.y;
        Bs[lk + 2][lr] = bv.z; Bs[lk + 3][lr] = bv.w;
        __syncthreads();

#pragma unroll
        for (int k = 0; k < 8; k++) {
            float a[8], bb[8];
            *(float4*)(a)      = *(const float4*)&As[k][tm];
            *(float4*)(a + 4)  = *(const float4*)&As[k][tm + 4];
            *(float4*)(bb)     = *(const float4*)&Bs[k][tn];
            *(float4*)(bb + 4) = *(const float4*)&Bs[k][tn + 4];
#pragma unroll
            for (int i = 0; i < 8; i++)
#pragma unroll
                for (int j = 0; j < 8; j++)
                    acc[i][j] += a[i] * bb[j];
        }
        __syncthreads();
    }

    // epilogue
#pragma unroll
    for (int i = 0; i < 8; i++) {
        const int m = bm + tm + i;
        if (m < M) {
            float* crow = C + (size_t)m * N + bn + tn;
#pragma unroll
            for (int j = 0; j < 8; j += 4) {
                float4 v;
                v.x = acc[i][j + 0]; v.y = acc[i][j + 1];
                v.z = acc[i][j + 2]; v.w = acc[i][j + 3];
                if (EPI) {
                    const int n = bn + tn + j;
                    const float4 bz = *(const float4*)&bias[n];
                    const float4 rz = *(const float4*)&res[(size_t)m * N + n];
                    v.x += bz.x + rz.x; v.y += bz.y + rz.y;
                    v.z += bz.z + rz.z; v.w += bz.w + rz.w;
                }
                *(float4*)(crow + j) = v;
            }
        }
    }
}

// ---------------------------------------------------------------------------
// Attention: one block per (b,h). K,V staged in smem; per-warp query rows.
// scores = (q . k) * scale[h]; diag masked; softmax; out = P @ V.
// ---------------------------------------------------------------------------
#define KSTRIDE 68   // pad K rows: float4-aligned, conflict-free across lanes

__global__ __launch_bounds__(256, 1)
void attn_kernel(const float* __restrict__ qkv, const float* __restrict__ scale,
                 float* __restrict__ attout)
{
    const int bh = blockIdx.x;
    const int b = bh / HEADS;
    const int h = bh % HEADS;
    const float sc = scale[h];

    extern __shared__ float sm[];
    float* Ks = sm;                       // SEQ * KSTRIDE
    float* Vs = Ks + SEQ * KSTRIDE;       // SEQ * 64
    float* qs = Vs + SEQ * HD;            // 8 * 64
    float* ps = qs + 8 * HD;              // 8 * 200

    const float* base = qkv + (size_t)b * SEQ * QKV_N;

    // stage K and V (coalesced: 64 consecutive floats per row)
    for (int idx = threadIdx.x; idx < SEQ * HD; idx += blockDim.x) {
        const int j = idx >> 6, d = idx & 63;
        const size_t ro = (size_t)j * QKV_N + h * HD + d;
        Ks[j * KSTRIDE + d] = base[ro + DIM];
        Vs[j * HD + d]      = base[ro + 2 * DIM];
    }
    __syncthreads();

    const int warp = threadIdx.x >> 5;
    const int lane = threadIdx.x & 31;
    float* qw = qs + warp * HD;
    float* pw = ps + warp * 200;

    for (int i = warp; i < SEQ; i += 8) {
        // load q row (64 floats, 16 lanes x float4)
        if (lane < 16) {
            *(float4*)&qw[lane * 4] =
                *(const float4*)&base[(size_t)i * QKV_N + h * HD + lane * 4];
        }
        __syncwarp();

        // scores + row max (lane-strided over j)
        float lmax = -1e30f;
#pragma unroll
        for (int jj = 0; jj < 7; jj++) {
            const int j = lane + jj * 32;
            if (j < SEQ) {
                const float4* kr = (const float4*)&Ks[j * KSTRIDE];
                const float4* qr = (const float4*)qw;
                float s = 0.f;
#pragma unroll
                for (int d4 = 0; d4 < 16; d4++) {
                    const float4 kk = kr[d4];
                    const float4 qq = qr[d4];
                    s += kk.x * qq.x + kk.y * qq.y + kk.z * qq.z + kk.w * qq.w;
                }
                s *= sc;
                if (j == i) s = -1e30f;   // diagonal self-mask
                pw[j] = s;
                lmax = fmaxf(lmax, s);
            }
        }
#pragma unroll
        for (int o = 16; o; o >>= 1)
            lmax = fmaxf(lmax, __shfl_xor_sync(0xffffffffu, lmax, o));

        // exp + sum
        float lsum = 0.f;
#pragma unroll
        for (int jj = 0; jj < 7; jj++) {
            const int j = lane + jj * 32;
            if (j < SEQ) {
                const float e = __expf(pw[j] - lmax);
                pw[j] = e;
                lsum += e;
            }
        }
#pragma unroll
        for (int o = 16; o; o >>= 1)
            lsum += __shfl_xor_sync(0xffffffffu, lsum, o);
        const float inv = 1.f / lsum;
        __syncwarp();

        // out = P @ V : lanes over head-dim, broadcast p[j]
        float acc0 = 0.f, acc1 = 0.f;
        for (int j = 0; j < SEQ; j++) {
            const float p = pw[j];
            acc0 += p * Vs[j * HD + lane];
            acc1 += p * Vs[j * HD + lane + 32];
        }
        float* orow = attout + (size_t)(b * SEQ + i) * DIM + h * HD;
        orow[lane]      = acc0 * inv;
        orow[lane + 32] = acc1 * inv;
        __syncwarp();   // protect pw/qw reuse next iteration
    }
}

// ---------------------------------------------------------------------------
extern "C" void kernel_launch(void* const* d_in, const int* in_sizes, int n_in,
                              void* d_out, int out_size)
{
    const float* x      = (const float*)d_in[0];   // [64,197,768]
    const float* scale  = (const float*)d_in[1];   // [12]
    const float* w_qkv  = (const float*)d_in[2];   // [2304,768]
    const float* w_proj = (const float*)d_in[3];   // [768,768]
    const float* b_proj = (const float*)d_in[4];   // [768]
    float* out = (float*)d_out;                    // [64,197,768]

    float *qkv, *att;
    cudaGetSymbolAddress((void**)&qkv, g_qkv);
    cudaGetSymbolAddress((void**)&att, g_att);

    // 1) qkv = x @ w_qkv^T
    dim3 g1((M_TOT + 127) / 128, QKV_N / 128);
    sgemm_nt<false><<<g1, 256>>>(x, w_qkv, qkv, M_TOT, QKV_N, DIM, nullptr, nullptr);

    // 2) attention per (b,h)
    const size_t smem = (size_t)(SEQ * KSTRIDE + SEQ * HD + 8 * HD + 8 * 200) * sizeof(float);
    cudaFuncSetAttribute(attn_kernel, cudaFuncAttributeMaxDynamicSharedMemorySize, (int)smem);
    attn_kernel<<<BATCH * HEADS, 256, smem>>>(qkv, scale, att);

    // 3) out = att @ w_proj^T + b_proj + x
    dim3 g2((M_TOT + 127) / 128, DIM / 128);
    sgemm_nt<true><<<g2, 256>>>(att, w_proj, out, M_TOT, DIM, DIM, b_proj, x);
}

// round 3
// speedup vs baseline: 1.9426x; 1.9426x over previous
#include <cuda_runtime.h>
#include <cuda_bf16.h>
#include <cstdint>

// Problem constants
#define BATCH 64
#define SEQ   197
#define DIM   768
#define HEADS 12
#define HD    64
#define M_TOT (BATCH * SEQ)      // 12608
#define QKV_N (3 * DIM)          // 2304
#define KDIM  768

// Scratch
__device__ float g_qkv[(size_t)M_TOT * QKV_N];   // ~116 MB
__device__ float g_att[(size_t)M_TOT * DIM];     // ~39 MB

__device__ __forceinline__ uint32_t smem_u32(const void* p) {
    uint32_t a;
    asm("{ .reg .u64 t; cvta.to.shared.u64 t, %1; cvt.u32.u64 %0, t; }" : "=r"(a) : "l"(p));
    return a;
}

// ---------------------------------------------------------------------------
// tf32 mma.sync GEMM (NT): C[m,n] = sum_k A[m,k]*B[n,k] (+bias[n]+res if EPI)
// CTA 128x128, 8 warps (2x4), warp tile 64x32, K-chunk 32, 2-stage cp.async.
// Smem rows padded to 36 floats -> conflict-free fragment loads.
// ---------------------------------------------------------------------------
#define MT 128
#define NTL 128
#define KC 32
#define NKT (KDIM / KC)           // 24
#define ROWSTRIDE 36
#define STG_FLOATS (2 * 128 * ROWSTRIDE)            // A + B, one stage
#define GEMM_SMEM (2 * STG_FLOATS * 4)              // 73728 bytes

__device__ __forceinline__ void mma_tf32(float* c, uint32_t a0, uint32_t a1,
                                         uint32_t a2, uint32_t a3,
                                         uint32_t b0, uint32_t b1) {
    asm volatile(
        "mma.sync.aligned.m16n8k8.row.col.f32.tf32.tf32.f32 "
        "{%0,%1,%2,%3}, {%4,%5,%6,%7}, {%8,%9}, {%0,%1,%2,%3};"
        : "+f"(c[0]), "+f"(c[1]), "+f"(c[2]), "+f"(c[3])
        : "r"(a0), "r"(a1), "r"(a2), "r"(a3), "r"(b0), "r"(b1));
}

template <bool EPI>
__global__ __launch_bounds__(256, 2)
void tf32_gemm(const float* __restrict__ A, const float* __restrict__ B,
               float* __restrict__ C, int M, int Ng,
               const float* __restrict__ bias, const float* __restrict__ res)
{
    extern __shared__ float sm[];
    const int tid = threadIdx.x;
    const int bm = blockIdx.x * MT;
    const int bn = blockIdx.y * NTL;

    const int w = tid >> 5, lane = tid & 31;
    const int wm = (w & 1) * 64;      // warp m offset
    const int wn = (w >> 1) * 32;     // warp n offset
    const int g = lane >> 2;          // group id 0..7
    const int tk = lane & 3;          // thread-in-group 0..3

    float acc[4][4][4];
#pragma unroll
    for (int i = 0; i < 4; i++)
#pragma unroll
        for (int j = 0; j < 4; j++)
#pragma unroll
            for (int q = 0; q < 4; q++) acc[i][j][q] = 0.f;

    // ---- async stage loader ----
    auto load_stage = [&](int s, int kt) {
        float* As = sm + s * STG_FLOATS;
        float* Bs = As + 128 * ROWSTRIDE;
        const int k0 = kt * KC;
#pragma unroll
        for (int c = 0; c < 4; c++) {
            const int ch = tid + c * 256;          // 0..1023
            const int row = ch >> 3, kq = ch & 7;
            const int m = bm + row;
            const float* src = A + (size_t)(m < M ? m : M - 1) * KDIM + k0 + kq * 4;
            const uint32_t dst = smem_u32(As + row * ROWSTRIDE + kq * 4);
            const int sz = (m < M) ? 16 : 0;
            asm volatile("cp.async.cg.shared.global [%0], [%1], 16, %2;"
                         :: "r"(dst), "l"(src), "r"(sz) : "memory");
        }
#pragma unroll
        for (int c = 0; c < 4; c++) {
            const int ch = tid + c * 256;
            const int row = ch >> 3, kq = ch & 7;
            const float* src = B + (size_t)(bn + row) * KDIM + k0 + kq * 4;
            const uint32_t dst = smem_u32(Bs + row * ROWSTRIDE + kq * 4);
            asm volatile("cp.async.cg.shared.global [%0], [%1], 16, 16;"
                         :: "r"(dst), "l"(src) : "memory");
        }
    };

    load_stage(0, 0);
    asm volatile("cp.async.commit_group;" ::: "memory");

    for (int kt = 0; kt < NKT; kt++) {
        if (kt + 1 < NKT) load_stage((kt + 1) & 1, kt + 1);
        asm volatile("cp.async.commit_group;" ::: "memory");
        asm volatile("cp.async.wait_group 1;" ::: "memory");
        __syncthreads();

        const float* As = sm + (kt & 1) * STG_FLOATS;
        const float* Bs = As + 128 * ROWSTRIDE;

#pragma unroll
        for (int ks = 0; ks < 4; ks++) {
            const int kb = ks * 8;
            uint32_t af[4][4], bf[4][2];
#pragma unroll
            for (int mt = 0; mt < 4; mt++) {
                const float* ap = As + (wm + mt * 16 + g) * ROWSTRIDE + kb + tk;
                af[mt][0] = __float_as_uint(ap[0]);
                af[mt][1] = __float_as_uint(ap[8 * ROWSTRIDE]);
                af[mt][2] = __float_as_uint(ap[4]);
                af[mt][3] = __float_as_uint(ap[8 * ROWSTRIDE + 4]);
            }
#pragma unroll
            for (int nt = 0; nt < 4; nt++) {
                const float* bp = Bs + (wn + nt * 8 + g) * ROWSTRIDE + kb + tk;
                bf[nt][0] = __float_as_uint(bp[0]);
                bf[nt][1] = __float_as_uint(bp[4]);
            }
#pragma unroll
            for (int mt = 0; mt < 4; mt++)
#pragma unroll
                for (int nt = 0; nt < 4; nt++)
                    mma_tf32(acc[mt][nt], af[mt][0], af[mt][1], af[mt][2], af[mt][3],
                             bf[nt][0], bf[nt][1]);
        }
        __syncthreads();
    }

    // ---- epilogue ----
#pragma unroll
    for (int mt = 0; mt < 4; mt++) {
#pragma unroll
        for (int half = 0; half < 2; half++) {
            const int m = bm + wm + mt * 16 + g + half * 8;
            if (m < M) {
#pragma unroll
                for (int nt = 0; nt < 4; nt++) {
                    const int n = bn + wn + nt * 8 + 2 * tk;
                    float2 v;
                    v.x = acc[mt][nt][half * 2 + 0];
                    v.y = acc[mt][nt][half * 2 + 1];
                    if (EPI) {
                        const float2 bz = *(const float2*)&bias[n];
                        const float2 rz = *(const float2*)&res[(size_t)m * Ng + n];
                        v.x += bz.x + rz.x;
                        v.y += bz.y + rz.y;
                    }
                    *(float2*)&C[(size_t)m * Ng + n] = v;
                }
            }
        }
    }
}

// ---------------------------------------------------------------------------
// Attention: one block per (b,h). (unchanged from R1 — passed)
// ---------------------------------------------------------------------------
#define KSTRIDE 68

__global__ __launch_bounds__(256, 1)
void attn_kernel(const float* __restrict__ qkv, const float* __restrict__ scale,
                 float* __restrict__ attout)
{
    const int bh = blockIdx.x;
    const int b = bh / HEADS;
    const int h = bh % HEADS;
    const float sc = scale[h];

    extern __shared__ float sm[];
    float* Ks = sm;
    float* Vs = Ks + SEQ * KSTRIDE;
    float* qs = Vs + SEQ * HD;
    float* ps = qs + 8 * HD;

    const float* base = qkv + (size_t)b * SEQ * QKV_N;

    for (int idx = threadIdx.x; idx < SEQ * HD; idx += blockDim.x) {
        const int j = idx >> 6, d = idx & 63;
        const size_t ro = (size_t)j * QKV_N + h * HD + d;
        Ks[j * KSTRIDE + d] = base[ro + DIM];
        Vs[j * HD + d]      = base[ro + 2 * DIM];
    }
    __syncthreads();

    const int warp = threadIdx.x >> 5;
    const int lane = threadIdx.x & 31;
    float* qw = qs + warp * HD;
    float* pw = ps + warp * 200;

    for (int i = warp; i < SEQ; i += 8) {
        if (lane < 16) {
            *(float4*)&qw[lane * 4] =
                *(const float4*)&base[(size_t)i * QKV_N + h * HD + lane * 4];
        }
        __syncwarp();

        float lmax = -1e30f;
#pragma unroll
        for (int jj = 0; jj < 7; jj++) {
            const int j = lane + jj * 32;
            if (j < SEQ) {
                const float4* kr = (const float4*)&Ks[j * KSTRIDE];
                const float4* qr = (const float4*)qw;
                float s = 0.f;
#pragma unroll
                for (int d4 = 0; d4 < 16; d4++) {
                    const float4 kk = kr[d4];
                    const float4 qq = qr[d4];
                    s += kk.x * qq.x + kk.y * qq.y + kk.z * qq.z + kk.w * qq.w;
                }
                s *= sc;
                if (j == i) s = -1e30f;
                pw[j] = s;
                lmax = fmaxf(lmax, s);
            }
        }
#pragma unroll
        for (int o = 16; o; o >>= 1)
            lmax = fmaxf(lmax, __shfl_xor_sync(0xffffffffu, lmax, o));

        float lsum = 0.f;
#pragma unroll
        for (int jj = 0; jj < 7; jj++) {
            const int j = lane + jj * 32;
            if (j < SEQ) {
                const float e = __expf(pw[j] - lmax);
                pw[j] = e;
                lsum += e;
            }
        }
#pragma unroll
        for (int o = 16; o; o >>= 1)
            lsum += __shfl_xor_sync(0xffffffffu, lsum, o);
        const float inv = 1.f / lsum;
        __syncwarp();

        float acc0 = 0.f, acc1 = 0.f;
        for (int j = 0; j < SEQ; j++) {
            const float p = pw[j];
            acc0 += p * Vs[j * HD + lane];
            acc1 += p * Vs[j * HD + lane + 32];
        }
        float* orow = attout + (size_t)(b * SEQ + i) * DIM + h * HD;
        orow[lane]      = acc0 * inv;
        orow[lane + 32] = acc1 * inv;
        __syncwarp();
    }
}

// ---------------------------------------------------------------------------
extern "C" void kernel_launch(void* const* d_in, const int* in_sizes, int n_in,
                              void* d_out, int out_size)
{
    const float* x      = (const float*)d_in[0];
    const float* scale  = (const float*)d_in[1];
    const float* w_qkv  = (const float*)d_in[2];
    const float* w_proj = (const float*)d_in[3];
    const float* b_proj = (const float*)d_in[4];
    float* out = (float*)d_out;

    float *qkv, *att;
    cudaGetSymbolAddress((void**)&qkv, g_qkv);
    cudaGetSymbolAddress((void**)&att, g_att);

    cudaFuncSetAttribute(tf32_gemm<false>,
                         cudaFuncAttributeMaxDynamicSharedMemorySize, GEMM_SMEM);
    cudaFuncSetAttribute(tf32_gemm<true>,
                         cudaFuncAttributeMaxDynamicSharedMemorySize, GEMM_SMEM);
    const size_t asmem = (size_t)(SEQ * KSTRIDE + SEQ * HD + 8 * HD + 8 * 200) * sizeof(float);
    cudaFuncSetAttribute(attn_kernel,
                         cudaFuncAttributeMaxDynamicSharedMemorySize, (int)asmem);

    // 1) qkv = x @ w_qkv^T  (tf32 mma.sync)
    dim3 g1((M_TOT + MT - 1) / MT, QKV_N / NTL);
    tf32_gemm<false><<<g1, 256, GEMM_SMEM>>>(x, w_qkv, qkv, M_TOT, QKV_N, nullptr, nullptr);

    // 2) attention per (b,h)
    attn_kernel<<<BATCH * HEADS, 256, asmem>>>(qkv, scale, att);

    // 3) out = att @ w_proj^T + b_proj + x  (tf32 mma.sync, fused epilogue)
    dim3 g2((M_TOT + MT - 1) / MT, DIM / NTL);
    tf32_gemm<true><<<g2, 256, GEMM_SMEM>>>(att, w_proj, out, M_TOT, DIM, b_proj, x);
}

// round 4
// speedup vs baseline: 4.0130x; 2.0658x over previous
#include <cuda_runtime.h>
#include <cuda_bf16.h>
#include <cstdint>

// Problem constants
#define BATCH 64
#define SEQ   197
#define DIM   768
#define HEADS 12
#define HD    64
#define M_TOT (BATCH * SEQ)      // 12608
#define QKV_N (3 * DIM)          // 2304
#define KDIM  768

// Scratch
__device__ float g_qkv[(size_t)M_TOT * QKV_N];   // ~116 MB
__device__ float g_att[(size_t)M_TOT * DIM];     // ~39 MB

__device__ __forceinline__ uint32_t smem_u32(const void* p) {
    uint32_t a;
    asm("{ .reg .u64 t; cvta.to.shared.u64 t, %1; cvt.u32.u64 %0, t; }" : "=r"(a) : "l"(p));
    return a;
}

__device__ __forceinline__ void mma_tf32(float* c, uint32_t a0, uint32_t a1,
                                         uint32_t a2, uint32_t a3,
                                         uint32_t b0, uint32_t b1) {
    asm volatile(
        "mma.sync.aligned.m16n8k8.row.col.f32.tf32.tf32.f32 "
        "{%0,%1,%2,%3}, {%4,%5,%6,%7}, {%8,%9}, {%0,%1,%2,%3};"
        : "+f"(c[0]), "+f"(c[1]), "+f"(c[2]), "+f"(c[3])
        : "r"(a0), "r"(a1), "r"(a2), "r"(a3), "r"(b0), "r"(b1));
}

// ---------------------------------------------------------------------------
// tf32 mma.sync GEMM (NT) — unchanged from R3 (passed, tensor-paced)
// ---------------------------------------------------------------------------
#define MT 128
#define NTL 128
#define KC 32
#define NKT (KDIM / KC)           // 24
#define ROWSTRIDE 36
#define STG_FLOATS (2 * 128 * ROWSTRIDE)
#define GEMM_SMEM (2 * STG_FLOATS * 4)              // 73728 bytes

template <bool EPI>
__global__ __launch_bounds__(256, 2)
void tf32_gemm(const float* __restrict__ A, const float* __restrict__ B,
               float* __restrict__ C, int M, int Ng,
               const float* __restrict__ bias, const float* __restrict__ res)
{
    extern __shared__ float sm[];
    const int tid = threadIdx.x;
    const int bm = blockIdx.x * MT;
    const int bn = blockIdx.y * NTL;

    const int w = tid >> 5, lane = tid & 31;
    const int wm = (w & 1) * 64;
    const int wn = (w >> 1) * 32;
    const int g = lane >> 2;
    const int tk = lane & 3;

    float acc[4][4][4];
#pragma unroll
    for (int i = 0; i < 4; i++)
#pragma unroll
        for (int j = 0; j < 4; j++)
#pragma unroll
            for (int q = 0; q < 4; q++) acc[i][j][q] = 0.f;

    auto load_stage = [&](int s, int kt) {
        float* As = sm + s * STG_FLOATS;
        float* Bs = As + 128 * ROWSTRIDE;
        const int k0 = kt * KC;
#pragma unroll
        for (int c = 0; c < 4; c++) {
            const int ch = tid + c * 256;
            const int row = ch >> 3, kq = ch & 7;
            const int m = bm + row;
            const float* src = A + (size_t)(m < M ? m : M - 1) * KDIM + k0 + kq * 4;
            const uint32_t dst = smem_u32(As + row * ROWSTRIDE + kq * 4);
            const int sz = (m < M) ? 16 : 0;
            asm volatile("cp.async.cg.shared.global [%0], [%1], 16, %2;"
                         :: "r"(dst), "l"(src), "r"(sz) : "memory");
        }
#pragma unroll
        for (int c = 0; c < 4; c++) {
            const int ch = tid + c * 256;
            const int row = ch >> 3, kq = ch & 7;
            const float* src = B + (size_t)(bn + row) * KDIM + k0 + kq * 4;
            const uint32_t dst = smem_u32(Bs + row * ROWSTRIDE + kq * 4);
            asm volatile("cp.async.cg.shared.global [%0], [%1], 16, 16;"
                         :: "r"(dst), "l"(src) : "memory");
        }
    };

    load_stage(0, 0);
    asm volatile("cp.async.commit_group;" ::: "memory");

    for (int kt = 0; kt < NKT; kt++) {
        if (kt + 1 < NKT) load_stage((kt + 1) & 1, kt + 1);
        asm volatile("cp.async.commit_group;" ::: "memory");
        asm volatile("cp.async.wait_group 1;" ::: "memory");
        __syncthreads();

        const float* As = sm + (kt & 1) * STG_FLOATS;
        const float* Bs = As + 128 * ROWSTRIDE;

#pragma unroll
        for (int ks = 0; ks < 4; ks++) {
            const int kb = ks * 8;
            uint32_t af[4][4], bf[4][2];
#pragma unroll
            for (int mt = 0; mt < 4; mt++) {
                const float* ap = As + (wm + mt * 16 + g) * ROWSTRIDE + kb + tk;
                af[mt][0] = __float_as_uint(ap[0]);
                af[mt][1] = __float_as_uint(ap[8 * ROWSTRIDE]);
                af[mt][2] = __float_as_uint(ap[4]);
                af[mt][3] = __float_as_uint(ap[8 * ROWSTRIDE + 4]);
            }
#pragma unroll
            for (int nt = 0; nt < 4; nt++) {
                const float* bp = Bs + (wn + nt * 8 + g) * ROWSTRIDE + kb + tk;
                bf[nt][0] = __float_as_uint(bp[0]);
                bf[nt][1] = __float_as_uint(bp[4]);
            }
#pragma unroll
            for (int mt = 0; mt < 4; mt++)
#pragma unroll
                for (int nt = 0; nt < 4; nt++)
                    mma_tf32(acc[mt][nt], af[mt][0], af[mt][1], af[mt][2], af[mt][3],
                             bf[nt][0], bf[nt][1]);
        }
        __syncthreads();
    }

#pragma unroll
    for (int mt = 0; mt < 4; mt++) {
#pragma unroll
        for (int half = 0; half < 2; half++) {
            const int m = bm + wm + mt * 16 + g + half * 8;
            if (m < M) {
#pragma unroll
                for (int nt = 0; nt < 4; nt++) {
                    const int n = bn + wn + nt * 8 + 2 * tk;
                    float2 v;
                    v.x = acc[mt][nt][half * 2 + 0];
                    v.y = acc[mt][nt][half * 2 + 1];
                    if (EPI) {
                        const float2 bz = *(const float2*)&bias[n];
                        const float2 rz = *(const float2*)&res[(size_t)m * Ng + n];
                        v.x += bz.x + rz.x;
                        v.y += bz.y + rz.y;
                    }
                    *(float2*)&C[(size_t)m * Ng + n] = v;
                }
            }
        }
    }
}

// ---------------------------------------------------------------------------
// mma.sync attention: one block per (b,h), 4 warps, 16 query rows per warp.
// S and P stay in registers; softmax via quad shuffles; V^T in smem for PV.
// ---------------------------------------------------------------------------
#define KS_STRIDE 68     // (4g+tk)%32 distinct  -> conflict-free B reads
#define VT_STRIDE 204    // (12g+tk)%32 distinct -> conflict-free B reads
#define JPAD 200         // 197 padded to 25 tiles of 8
#define ATT_SMEM ((JPAD * KS_STRIDE + HD * VT_STRIDE) * 4)   // 106624 B

__global__ __launch_bounds__(128)
void attn_mma(const float* __restrict__ qkv, const float* __restrict__ scale,
              float* __restrict__ attout)
{
    const int bh = blockIdx.x;
    const int b = bh / HEADS;
    const int h = bh % HEADS;
    const float sc = scale[h];

    extern __shared__ float sm[];
    float* Ks = sm;                         // [200][68]
    float* Vt = Ks + JPAD * KS_STRIDE;      // [64][204]

    const float* base = qkv + (size_t)b * SEQ * QKV_N;

    // stage K (row-major, zero-pad rows 197..199) and V transposed
    for (int idx = threadIdx.x; idx < JPAD * HD; idx += 128) {
        const int j = idx >> 6, d = idx & 63;
        float kv = 0.f, vv = 0.f;
        if (j < SEQ) {
            const size_t ro = (size_t)j * QKV_N + h * HD + d;
            kv = base[ro + DIM];
            vv = base[ro + 2 * DIM];
        }
        Ks[j * KS_STRIDE + d] = kv;
        Vt[d * VT_STRIDE + j] = vv;
    }
    __syncthreads();

    const int w = threadIdx.x >> 5;
    const int lane = threadIdx.x & 31;
    const int g = lane >> 2;
    const int tk = lane & 3;
    const int src0 = (lane & ~3) | (tk >> 1);   // shuffle source for col tk
    const int src1 = src0 + 2;                  // shuffle source for col tk+4
    const bool hi = (tk & 1);

    for (int rb = 0; rb < 4; rb++) {
        const int rowbase = rb * 64 + w * 16;
        const int rlo = rowbase + g;            // global query rows
        const int rhi = rowbase + g + 8;
        const int rlo_c = rlo < SEQ ? rlo : SEQ - 1;
        const int rhi_c = rhi < SEQ ? rhi : SEQ - 1;

        // Q fragments for all 8 k-steps (HD=64)
        uint32_t qa[8][4];
        const float* q0 = base + (size_t)rlo_c * QKV_N + h * HD;
        const float* q1 = base + (size_t)rhi_c * QKV_N + h * HD;
#pragma unroll
        for (int ks = 0; ks < 8; ks++) {
            const int kb = ks * 8;
            qa[ks][0] = __float_as_uint(q0[kb + tk]);
            qa[ks][1] = __float_as_uint(q1[kb + tk]);
            qa[ks][2] = __float_as_uint(q0[kb + tk + 4]);
            qa[ks][3] = __float_as_uint(q1[kb + tk + 4]);
        }

        // S = Q @ K^T : 25 n-tiles x 8 k-steps
        float S[25][4];
#pragma unroll
        for (int nt = 0; nt < 25; nt++) {
            S[nt][0] = S[nt][1] = S[nt][2] = S[nt][3] = 0.f;
#pragma unroll
            for (int ks = 0; ks < 8; ks++) {
                const float* bp = Ks + (nt * 8 + g) * KS_STRIDE + ks * 8 + tk;
                mma_tf32(S[nt], qa[ks][0], qa[ks][1], qa[ks][2], qa[ks][3],
                         __float_as_uint(bp[0]), __float_as_uint(bp[4]));
            }
        }

        // scale + diagonal / out-of-range mask
#pragma unroll
        for (int nt = 0; nt < 25; nt++) {
            const int j0 = nt * 8 + 2 * tk;
            const int j1 = j0 + 1;
            S[nt][0] = (j0 == rlo || j0 >= SEQ) ? -1e30f : S[nt][0] * sc;
            S[nt][1] = (j1 == rlo || j1 >= SEQ) ? -1e30f : S[nt][1] * sc;
            S[nt][2] = (j0 == rhi || j0 >= SEQ) ? -1e30f : S[nt][2] * sc;
            S[nt][3] = (j1 == rhi || j1 >= SEQ) ? -1e30f : S[nt][3] * sc;
        }

        // row max (quad reduction: lanes sharing g hold the same rows)
        float mlo = -1e30f, mhi = -1e30f;
#pragma unroll
        for (int nt = 0; nt < 25; nt++) {
            mlo = fmaxf(mlo, fmaxf(S[nt][0], S[nt][1]));
            mhi = fmaxf(mhi, fmaxf(S[nt][2], S[nt][3]));
        }
        mlo = fmaxf(mlo, __shfl_xor_sync(0xffffffffu, mlo, 1));
        mlo = fmaxf(mlo, __shfl_xor_sync(0xffffffffu, mlo, 2));
        mhi = fmaxf(mhi, __shfl_xor_sync(0xffffffffu, mhi, 1));
        mhi = fmaxf(mhi, __shfl_xor_sync(0xffffffffu, mhi, 2));

        // exp + row sum
        float slo = 0.f, shi = 0.f;
#pragma unroll
        for (int nt = 0; nt < 25; nt++) {
            S[nt][0] = __expf(S[nt][0] - mlo);
            S[nt][1] = __expf(S[nt][1] - mlo);
            S[nt][2] = __expf(S[nt][2] - mhi);
            S[nt][3] = __expf(S[nt][3] - mhi);
            slo += S[nt][0] + S[nt][1];
            shi += S[nt][2] + S[nt][3];
        }
        slo += __shfl_xor_sync(0xffffffffu, slo, 1);
        slo += __shfl_xor_sync(0xffffffffu, slo, 2);
        shi += __shfl_xor_sync(0xffffffffu, shi, 1);
        shi += __shfl_xor_sync(0xffffffffu, shi, 2);
        const float inv_lo = 1.f / slo;
        const float inv_hi = 1.f / shi;

        // out = P @ V : 25 k-steps x 8 n-tiles. P fragments via quad shuffles.
        float O[8][4];
#pragma unroll
        for (int dt = 0; dt < 8; dt++)
            O[dt][0] = O[dt][1] = O[dt][2] = O[dt][3] = 0.f;

#pragma unroll
        for (int kj = 0; kj < 25; kj++) {
            // accum layout cols {2tk, 2tk+1} -> A-frag cols {tk, tk+4}
            float v0a = __shfl_sync(0xffffffffu, S[kj][0], src0);
            float v1a = __shfl_sync(0xffffffffu, S[kj][1], src0);
            float v0b = __shfl_sync(0xffffffffu, S[kj][0], src1);
            float v1b = __shfl_sync(0xffffffffu, S[kj][1], src1);
            float w0a = __shfl_sync(0xffffffffu, S[kj][2], src0);
            float w1a = __shfl_sync(0xffffffffu, S[kj][3], src0);
            float w0b = __shfl_sync(0xffffffffu, S[kj][2], src1);
            float w1b = __shfl_sync(0xffffffffu, S[kj][3], src1);
            const uint32_t a0 = __float_as_uint(hi ? v1a : v0a);
            const uint32_t a2 = __float_as_uint(hi ? v1b : v0b);
            const uint32_t a1 = __float_as_uint(hi ? w1a : w0a);
            const uint32_t a3 = __float_as_uint(hi ? w1b : w0b);
#pragma unroll
            for (int dt = 0; dt < 8; dt++) {
                const float* bp = Vt + (dt * 8 + g) * VT_STRIDE + kj * 8 + tk;
                mma_tf32(O[dt], a0, a1, a2, a3,
                         __float_as_uint(bp[0]), __float_as_uint(bp[4]));
            }
        }

        // write (normalize by row sum)
        float* orow_lo = attout + (size_t)(b * SEQ + rlo) * DIM + h * HD;
        float* orow_hi = attout + (size_t)(b * SEQ + rhi) * DIM + h * HD;
#pragma unroll
        for (int dt = 0; dt < 8; dt++) {
            const int d = dt * 8 + 2 * tk;
            if (rlo < SEQ) {
                float2 v; v.x = O[dt][0] * inv_lo; v.y = O[dt][1] * inv_lo;
                *(float2*)&orow_lo[d] = v;
            }
            if (rhi < SEQ) {
                float2 v; v.x = O[dt][2] * inv_hi; v.y = O[dt][3] * inv_hi;
                *(float2*)&orow_hi[d] = v;
            }
        }
    }
}

// ---------------------------------------------------------------------------
extern "C" void kernel_launch(void* const* d_in, const int* in_sizes, int n_in,
                              void* d_out, int out_size)
{
    const float* x      = (const float*)d_in[0];
    const float* scale  = (const float*)d_in[1];
    const float* w_qkv  = (const float*)d_in[2];
    const float* w_proj = (const float*)d_in[3];
    const float* b_proj = (const float*)d_in[4];
    float* out = (float*)d_out;

    float *qkv, *att;
    cudaGetSymbolAddress((void**)&qkv, g_qkv);
    cudaGetSymbolAddress((void**)&att, g_att);

    cudaFuncSetAttribute(tf32_gemm<false>,
                         cudaFuncAttributeMaxDynamicSharedMemorySize, GEMM_SMEM);
    cudaFuncSetAttribute(tf32_gemm<true>,
                         cudaFuncAttributeMaxDynamicSharedMemorySize, GEMM_SMEM);
    cudaFuncSetAttribute(attn_mma,
                         cudaFuncAttributeMaxDynamicSharedMemorySize, ATT_SMEM);

    // 1) qkv = x @ w_qkv^T
    dim3 g1((M_TOT + MT - 1) / MT, QKV_N / NTL);
    tf32_gemm<false><<<g1, 256, GEMM_SMEM>>>(x, w_qkv, qkv, M_TOT, QKV_N, nullptr, nullptr);

    // 2) attention (mma.sync)
    attn_mma<<<BATCH * HEADS, 128, ATT_SMEM>>>(qkv, scale, att);

    // 3) out = att @ w_proj^T + b_proj + x
    dim3 g2((M_TOT + MT - 1) / MT, DIM / NTL);
    tf32_gemm<true><<<g2, 256, GEMM_SMEM>>>(att, w_proj, out, M_TOT, DIM, b_proj, x);
}

// round 5
// speedup vs baseline: 6.1075x; 1.5219x over previous
#include <cuda_runtime.h>
#include <cuda_bf16.h>
#include <cstdint>

// Problem constants
#define BATCH 64
#define SEQ   197
#define DIM   768
#define HEADS 12
#define HD    64
#define M_TOT (BATCH * SEQ)      // 12608
#define QKV_N (3 * DIM)          // 2304
#define KDIM  768

// Scratch
__device__ float         g_qkv[(size_t)M_TOT * QKV_N];    // fp32 qkv (~116 MB)
__device__ __nv_bfloat16 g_xb[(size_t)M_TOT * DIM];       // x in bf16
__device__ __nv_bfloat16 g_wqb[(size_t)QKV_N * KDIM];     // w_qkv bf16
__device__ __nv_bfloat16 g_wpb[(size_t)DIM * KDIM];       // w_proj bf16
__device__ __nv_bfloat16 g_attb[(size_t)M_TOT * DIM];     // attention out bf16

__device__ __forceinline__ uint32_t smem_u32(const void* p) {
    uint32_t a;
    asm("{ .reg .u64 t; cvta.to.shared.u64 t, %1; cvt.u32.u64 %0, t; }" : "=r"(a) : "l"(p));
    return a;
}

__device__ __forceinline__ void mma_tf32(float* c, uint32_t a0, uint32_t a1,
                                         uint32_t a2, uint32_t a3,
                                         uint32_t b0, uint32_t b1) {
    asm volatile(
        "mma.sync.aligned.m16n8k8.row.col.f32.tf32.tf32.f32 "
        "{%0,%1,%2,%3}, {%4,%5,%6,%7}, {%8,%9}, {%0,%1,%2,%3};"
        : "+f"(c[0]), "+f"(c[1]), "+f"(c[2]), "+f"(c[3])
        : "r"(a0), "r"(a1), "r"(a2), "r"(a3), "r"(b0), "r"(b1));
}

__device__ __forceinline__ void mma_bf16(float* c, const uint32_t* a,
                                         uint32_t b0, uint32_t b1) {
    asm volatile(
        "mma.sync.aligned.m16n8k16.row.col.f32.bf16.bf16.f32 "
        "{%0,%1,%2,%3}, {%4,%5,%6,%7}, {%8,%9}, {%0,%1,%2,%3};"
        : "+f"(c[0]), "+f"(c[1]), "+f"(c[2]), "+f"(c[3])
        : "r"(a[0]), "r"(a[1]), "r"(a[2]), "r"(a[3]), "r"(b0), "r"(b1));
}

#define LDSM4(r, addr) \
    asm volatile("ldmatrix.sync.aligned.m8n8.x4.shared.b16 {%0,%1,%2,%3}, [%4];" \
                 : "=r"((r)[0]), "=r"((r)[1]), "=r"((r)[2]), "=r"((r)[3]) : "r"(addr))

// ---------------------------------------------------------------------------
// fp32 -> bf16 conversion (vectorized, sizes divisible by 4)
// ---------------------------------------------------------------------------
__global__ void f32_to_bf16(const float* __restrict__ in,
                            __nv_bfloat16* __restrict__ out, int n4)
{
    const int i = blockIdx.x * blockDim.x + threadIdx.x;
    if (i < n4) {
        const float4 v = ((const float4*)in)[i];
        ((__nv_bfloat162*)out)[2 * i]     = __floats2bfloat162_rn(v.x, v.y);
        ((__nv_bfloat162*)out)[2 * i + 1] = __floats2bfloat162_rn(v.z, v.w);
    }
}

// ---------------------------------------------------------------------------
// bf16 mma.sync GEMM (NT): C[m,n] = sum_k A[m,k]*B[n,k] (+bias[n]+res if EPI)
// CTA 128x128, 8 warps (2x4), warp tile 64x32, K-chunk 64 bf16, 2-stage
// cp.async, ldmatrix fragment loads. C/bias/res in fp32.
// ---------------------------------------------------------------------------
#define MT 128
#define NTL 128
#define BKC 64                     // K elems per stage
#define BNKT (KDIM / BKC)          // 12
#define BROWB 144                  // smem row stride bytes (72 bf16: 64 + 8 pad)
#define BSTG (256 * BROWB)         // 36864 B per stage (A 128 rows + B 128 rows)
#define BGEMM_SMEM (2 * BSTG)      // 73728 B

template <bool EPI>
__global__ __launch_bounds__(256, 2)
void bf16_gemm(const __nv_bfloat16* __restrict__ A,
               const __nv_bfloat16* __restrict__ B,
               float* __restrict__ C, int M, int Ng,
               const float* __restrict__ bias, const float* __restrict__ res)
{
    extern __shared__ char smc[];
    const uint32_t sb = smem_u32(smc);

    const int tid = threadIdx.x;
    const int bm = blockIdx.x * MT;
    const int bn = blockIdx.y * NTL;

    const int w = tid >> 5, lane = tid & 31;
    const int wm = (w & 1) * 64;
    const int wn = (w >> 1) * 32;
    const int g = lane >> 2;
    const int tk = lane & 3;

    float acc[4][4][4];
#pragma unroll
    for (int i = 0; i < 4; i++)
#pragma unroll
        for (int j = 0; j < 4; j++)
#pragma unroll
            for (int q = 0; q < 4; q++) acc[i][j][q] = 0.f;

    auto load_stage = [&](int s, int kt) {
        const uint32_t Asm = sb + s * BSTG;
        const uint32_t Bsm = Asm + 128 * BROWB;
        const int k0 = kt * BKC;
#pragma unroll
        for (int c4 = 0; c4 < 4; c4++) {
            const int c = tid + c4 * 256;       // 0..1023
            const int row = c >> 3, kq = c & 7; // 8 x 16B per 128B row
            const int m = bm + row;
            const __nv_bfloat16* src =
                A + (size_t)(m < M ? m : M - 1) * KDIM + k0 + kq * 8;
            const uint32_t dst = Asm + row * BROWB + kq * 16;
            const int sz = (m < M) ? 16 : 0;    // zero-fill OOB rows
            asm volatile("cp.async.cg.shared.global [%0], [%1], 16, %2;"
                         :: "r"(dst), "l"(src), "r"(sz) : "memory");
        }
#pragma unroll
        for (int c4 = 0; c4 < 4; c4++) {
            const int c = tid + c4 * 256;
            const int row = c >> 3, kq = c & 7;
            const __nv_bfloat16* src =
                B + (size_t)(bn + row) * KDIM + k0 + kq * 8;
            const uint32_t dst = Bsm + row * BROWB + kq * 16;
            asm volatile("cp.async.cg.shared.global [%0], [%1], 16, 16;"
                         :: "r"(dst), "l"(src) : "memory");
        }
    };

    load_stage(0, 0);
    asm volatile("cp.async.commit_group;" ::: "memory");

    for (int kt = 0; kt < BNKT; kt++) {
        if (kt + 1 < BNKT) load_stage((kt + 1) & 1, kt + 1);
        asm volatile("cp.async.commit_group;" ::: "memory");
        asm volatile("cp.async.wait_group 1;" ::: "memory");
        __syncthreads();

        const uint32_t Asm = sb + (kt & 1) * BSTG;
        const uint32_t Bsm = Asm + 128 * BROWB;

#pragma unroll
        for (int ks = 0; ks < 4; ks++) {          // 4 x k16
            const int kb = ks * 32;               // byte offset (16 bf16)
            uint32_t af[4][4], bf[4][2];
#pragma unroll
            for (int mt = 0; mt < 4; mt++) {
                // lanes 0-15: rows, lanes 16-31: +16B col (k+8)
                const uint32_t a =
                    Asm + (wm + mt * 16 + (lane & 15)) * BROWB + (lane >> 4) * 16 + kb;
                LDSM4(af[mt], a);
            }
#pragma unroll
            for (int p = 0; p < 2; p++) {
                // 4 tiles: (nt=2p,klo),(2p,khi),(2p+1,klo),(2p+1,khi)
                const int t = lane >> 3;
                const int nr = wn + (2 * p + (t >> 1)) * 8 + (lane & 7);
                const uint32_t a = Bsm + nr * BROWB + (t & 1) * 16 + kb;
                uint32_t r[4];
                LDSM4(r, a);
                bf[2 * p][0] = r[0]; bf[2 * p][1] = r[1];
                bf[2 * p + 1][0] = r[2]; bf[2 * p + 1][1] = r[3];
            }
#pragma unroll
            for (int mt = 0; mt < 4; mt++)
#pragma unroll
                for (int nt = 0; nt < 4; nt++)
                    mma_bf16(acc[mt][nt], af[mt], bf[nt][0], bf[nt][1]);
        }
        __syncthreads();
    }

    // epilogue (fp32)
#pragma unroll
    for (int mt = 0; mt < 4; mt++) {
#pragma unroll
        for (int half = 0; half < 2; half++) {
            const int m = bm + wm + mt * 16 + g + half * 8;
            if (m < M) {
#pragma unroll
                for (int nt = 0; nt < 4; nt++) {
                    const int n = bn + wn + nt * 8 + 2 * tk;
                    float2 v;
                    v.x = acc[mt][nt][half * 2 + 0];
                    v.y = acc[mt][nt][half * 2 + 1];
                    if (EPI) {
                        const float2 bz = *(const float2*)&bias[n];
                        const float2 rz = *(const float2*)&res[(size_t)m * Ng + n];
                        v.x += bz.x + rz.x;
                        v.y += bz.y + rz.y;
                    }
                    *(float2*)&C[(size_t)m * Ng + n] = v;
                }
            }
        }
    }
}

// ---------------------------------------------------------------------------
// mma.sync attention (tf32, unchanged compute) — writes bf16 output
// ---------------------------------------------------------------------------
#define KS_STRIDE 68
#define VT_STRIDE 204
#define JPAD 200
#define ATT_SMEM ((JPAD * KS_STRIDE + HD * VT_STRIDE) * 4)

__global__ __launch_bounds__(128)
void attn_mma(const float* __restrict__ qkv, const float* __restrict__ scale,
              __nv_bfloat16* __restrict__ attout)
{
    const int bh = blockIdx.x;
    const int b = bh / HEADS;
    const int h = bh % HEADS;
    const float sc = scale[h];

    extern __shared__ float sm[];
    float* Ks = sm;
    float* Vt = Ks + JPAD * KS_STRIDE;

    const float* base = qkv + (size_t)b * SEQ * QKV_N;

    for (int idx = threadIdx.x; idx < JPAD * HD; idx += 128) {
        const int j = idx >> 6, d = idx & 63;
        float kv = 0.f, vv = 0.f;
        if (j < SEQ) {
            const size_t ro = (size_t)j * QKV_N + h * HD + d;
            kv = base[ro + DIM];
            vv = base[ro + 2 * DIM];
        }
        Ks[j * KS_STRIDE + d] = kv;
        Vt[d * VT_STRIDE + j] = vv;
    }
    __syncthreads();

    const int w = threadIdx.x >> 5;
    const int lane = threadIdx.x & 31;
    const int g = lane >> 2;
    const int tk = lane & 3;
    const int src0 = (lane & ~3) | (tk >> 1);
    const int src1 = src0 + 2;
    const bool hi = (tk & 1);

    for (int rb = 0; rb < 4; rb++) {
        const int rowbase = rb * 64 + w * 16;
        const int rlo = rowbase + g;
        const int rhi = rowbase + g + 8;
        const int rlo_c = rlo < SEQ ? rlo : SEQ - 1;
        const int rhi_c = rhi < SEQ ? rhi : SEQ - 1;

        uint32_t qa[8][4];
        const float* q0 = base + (size_t)rlo_c * QKV_N + h * HD;
        const float* q1 = base + (size_t)rhi_c * QKV_N + h * HD;
#pragma unroll
        for (int ks = 0; ks < 8; ks++) {
            const int kb = ks * 8;
            qa[ks][0] = __float_as_uint(q0[kb + tk]);
            qa[ks][1] = __float_as_uint(q1[kb + tk]);
            qa[ks][2] = __float_as_uint(q0[kb + tk + 4]);
            qa[ks][3] = __float_as_uint(q1[kb + tk + 4]);
        }

        float S[25][4];
#pragma unroll
        for (int nt = 0; nt < 25; nt++) {
            S[nt][0] = S[nt][1] = S[nt][2] = S[nt][3] = 0.f;
#pragma unroll
            for (int ks = 0; ks < 8; ks++) {
                const float* bp = Ks + (nt * 8 + g) * KS_STRIDE + ks * 8 + tk;
                mma_tf32(S[nt], qa[ks][0], qa[ks][1], qa[ks][2], qa[ks][3],
                         __float_as_uint(bp[0]), __float_as_uint(bp[4]));
            }
        }

#pragma unroll
        for (int nt = 0; nt < 25; nt++) {
            const int j0 = nt * 8 + 2 * tk;
            const int j1 = j0 + 1;
            S[nt][0] = (j0 == rlo || j0 >= SEQ) ? -1e30f : S[nt][0] * sc;
            S[nt][1] = (j1 == rlo || j1 >= SEQ) ? -1e30f : S[nt][1] * sc;
            S[nt][2] = (j0 == rhi || j0 >= SEQ) ? -1e30f : S[nt][2] * sc;
            S[nt][3] = (j1 == rhi || j1 >= SEQ) ? -1e30f : S[nt][3] * sc;
        }

        float mlo = -1e30f, mhi = -1e30f;
#pragma unroll
        for (int nt = 0; nt < 25; nt++) {
            mlo = fmaxf(mlo, fmaxf(S[nt][0], S[nt][1]));
            mhi = fmaxf(mhi, fmaxf(S[nt][2], S[nt][3]));
        }
        mlo = fmaxf(mlo, __shfl_xor_sync(0xffffffffu, mlo, 1));
        mlo = fmaxf(mlo, __shfl_xor_sync(0xffffffffu, mlo, 2));
        mhi = fmaxf(mhi, __shfl_xor_sync(0xffffffffu, mhi, 1));
        mhi = fmaxf(mhi, __shfl_xor_sync(0xffffffffu, mhi, 2));

        float slo = 0.f, shi = 0.f;
#pragma unroll
        for (int nt = 0; nt < 25; nt++) {
            S[nt][0] = __expf(S[nt][0] - mlo);
            S[nt][1] = __expf(S[nt][1] - mlo);
            S[nt][2] = __expf(S[nt][2] - mhi);
            S[nt][3] = __expf(S[nt][3] - mhi);
            slo += S[nt][0] + S[nt][1];
            shi += S[nt][2] + S[nt][3];
        }
        slo += __shfl_xor_sync(0xffffffffu, slo, 1);
        slo += __shfl_xor_sync(0xffffffffu, slo, 2);
        shi += __shfl_xor_sync(0xffffffffu, shi, 1);
        shi += __shfl_xor_sync(0xffffffffu, shi, 2);
        const float inv_lo = 1.f / slo;
        const float inv_hi = 1.f / shi;

        float O[8][4];
#pragma unroll
        for (int dt = 0; dt < 8; dt++)
            O[dt][0] = O[dt][1] = O[dt][2] = O[dt][3] = 0.f;

#pragma unroll
        for (int kj = 0; kj < 25; kj++) {
            float v0a = __shfl_sync(0xffffffffu, S[kj][0], src0);
            float v1a = __shfl_sync(0xffffffffu, S[kj][1], src0);
            float v0b = __shfl_sync(0xffffffffu, S[kj][0], src1);
            float v1b = __shfl_sync(0xffffffffu, S[kj][1], src1);
            float w0a = __shfl_sync(0xffffffffu, S[kj][2], src0);
            float w1a = __shfl_sync(0xffffffffu, S[kj][3], src0);
            float w0b = __shfl_sync(0xffffffffu, S[kj][2], src1);
            float w1b = __shfl_sync(0xffffffffu, S[kj][3], src1);
            const uint32_t a0 = __float_as_uint(hi ? v1a : v0a);
            const uint32_t a2 = __float_as_uint(hi ? v1b : v0b);
            const uint32_t a1 = __float_as_uint(hi ? w1a : w0a);
            const uint32_t a3 = __float_as_uint(hi ? w1b : w0b);
#pragma unroll
            for (int dt = 0; dt < 8; dt++) {
                const float* bp = Vt + (dt * 8 + g) * VT_STRIDE + kj * 8 + tk;
                mma_tf32(O[dt], a0, a1, a2, a3,
                         __float_as_uint(bp[0]), __float_as_uint(bp[4]));
            }
        }

        __nv_bfloat16* orow_lo = attout + (size_t)(b * SEQ + rlo) * DIM + h * HD;
        __nv_bfloat16* orow_hi = attout + (size_t)(b * SEQ + rhi) * DIM + h * HD;
#pragma unroll
        for (int dt = 0; dt < 8; dt++) {
            const int d = dt * 8 + 2 * tk;
            if (rlo < SEQ) {
                *(__nv_bfloat162*)&orow_lo[d] =
                    __floats2bfloat162_rn(O[dt][0] * inv_lo, O[dt][1] * inv_lo);
            }
            if (rhi < SEQ) {
                *(__nv_bfloat162*)&orow_hi[d] =
                    __floats2bfloat162_rn(O[dt][2] * inv_hi, O[dt][3] * inv_hi);
            }
        }
    }
}

// ---------------------------------------------------------------------------
extern "C" void kernel_launch(void* const* d_in, const int* in_sizes, int n_in,
                              void* d_out, int out_size)
{
    const float* x      = (const float*)d_in[0];
    const float* scale  = (const float*)d_in[1];
    const float* w_qkv  = (const float*)d_in[2];
    const float* w_proj = (const float*)d_in[3];
    const float* b_proj = (const float*)d_in[4];
    float* out = (float*)d_out;

    float* qkv;            cudaGetSymbolAddress((void**)&qkv, g_qkv);
    __nv_bfloat16* xb;     cudaGetSymbolAddress((void**)&xb, g_xb);
    __nv_bfloat16* wqb;    cudaGetSymbolAddress((void**)&wqb, g_wqb);
    __nv_bfloat16* wpb;    cudaGetSymbolAddress((void**)&wpb, g_wpb);
    __nv_bfloat16* attb;   cudaGetSymbolAddress((void**)&attb, g_attb);

    cudaFuncSetAttribute(bf16_gemm<false>,
                         cudaFuncAttributeMaxDynamicSharedMemorySize, BGEMM_SMEM);
    cudaFuncSetAttribute(bf16_gemm<true>,
                         cudaFuncAttributeMaxDynamicSharedMemorySize, BGEMM_SMEM);
    cudaFuncSetAttribute(attn_mma,
                         cudaFuncAttributeMaxDynamicSharedMemorySize, ATT_SMEM);

    // 0) fp32 -> bf16 conversions
    {
        int n4 = (M_TOT * DIM) / 4;
        f32_to_bf16<<<(n4 + 255) / 256, 256>>>(x, xb, n4);
        n4 = (QKV_N * KDIM) / 4;
        f32_to_bf16<<<(n4 + 255) / 256, 256>>>(w_qkv, wqb, n4);
        n4 = (DIM * KDIM) / 4;
        f32_to_bf16<<<(n4 + 255) / 256, 256>>>(w_proj, wpb, n4);
    }

    // 1) qkv = x @ w_qkv^T  (bf16 mma)
    dim3 g1((M_TOT + MT - 1) / MT, QKV_N / NTL);
    bf16_gemm<false><<<g1, 256, BGEMM_SMEM>>>(xb, wqb, qkv, M_TOT, QKV_N,
                                              nullptr, nullptr);

    // 2) attention (tf32 mma), writes bf16
    attn_mma<<<BATCH * HEADS, 128, ATT_SMEM>>>(qkv, scale, attb);

    // 3) out = att @ w_proj^T + b_proj + x  (bf16 mma, fp32 epilogue)
    dim3 g2((M_TOT + MT - 1) / MT, DIM / NTL);
    bf16_gemm<true><<<g2, 256, BGEMM_SMEM>>>(attb, wpb, out, M_TOT, DIM,
                                             b_proj, x);
}

// round 6
// speedup vs baseline: 7.9376x; 1.2997x over previous
#include <cuda_runtime.h>
#include <cuda_bf16.h>
#include <cstdint>

// Problem constants
#define BATCH 64
#define SEQ   197
#define DIM   768
#define HEADS 12
#define HD    64
#define M_TOT (BATCH * SEQ)      // 12608
#define QKV_N (3 * DIM)          // 2304
#define KDIM  768

// Scratch (bf16 end-to-end between GEMMs)
__device__ __nv_bfloat16 g_qkvb[(size_t)M_TOT * QKV_N];   // qkv bf16 (~58 MB)
__device__ __nv_bfloat16 g_xb[(size_t)M_TOT * DIM];
__device__ __nv_bfloat16 g_wqb[(size_t)QKV_N * KDIM];
__device__ __nv_bfloat16 g_wpb[(size_t)DIM * KDIM];
__device__ __nv_bfloat16 g_attb[(size_t)M_TOT * DIM];

__device__ __forceinline__ uint32_t smem_u32(const void* p) {
    uint32_t a;
    asm("{ .reg .u64 t; cvta.to.shared.u64 t, %1; cvt.u32.u64 %0, t; }" : "=r"(a) : "l"(p));
    return a;
}

__device__ __forceinline__ void mma_bf16(float* c, const uint32_t* a,
                                         uint32_t b0, uint32_t b1) {
    asm volatile(
        "mma.sync.aligned.m16n8k16.row.col.f32.bf16.bf16.f32 "
        "{%0,%1,%2,%3}, {%4,%5,%6,%7}, {%8,%9}, {%0,%1,%2,%3};"
        : "+f"(c[0]), "+f"(c[1]), "+f"(c[2]), "+f"(c[3])
        : "r"(a[0]), "r"(a[1]), "r"(a[2]), "r"(a[3]), "r"(b0), "r"(b1));
}

#define LDSM4(r, addr) \
    asm volatile("ldmatrix.sync.aligned.m8n8.x4.shared.b16 {%0,%1,%2,%3}, [%4];" \
                 : "=r"((r)[0]), "=r"((r)[1]), "=r"((r)[2]), "=r"((r)[3]) : "r"(addr))
#define LDSM4T(r, addr) \
    asm volatile("ldmatrix.sync.aligned.m8n8.x4.trans.shared.b16 {%0,%1,%2,%3}, [%4];" \
                 : "=r"((r)[0]), "=r"((r)[1]), "=r"((r)[2]), "=r"((r)[3]) : "r"(addr))

__device__ __forceinline__ uint32_t pack_bf16(float lo, float hi) {
    __nv_bfloat162 v = __floats2bfloat162_rn(lo, hi);
    return *(uint32_t*)&v;
}

// ---------------------------------------------------------------------------
// fp32 -> bf16 conversion
// ---------------------------------------------------------------------------
__global__ void f32_to_bf16(const float* __restrict__ in,
                            __nv_bfloat16* __restrict__ out, int n4)
{
    const int i = blockIdx.x * blockDim.x + threadIdx.x;
    if (i < n4) {
        const float4 v = ((const float4*)in)[i];
        ((__nv_bfloat162*)out)[2 * i]     = __floats2bfloat162_rn(v.x, v.y);
        ((__nv_bfloat162*)out)[2 * i + 1] = __floats2bfloat162_rn(v.z, v.w);
    }
}

// ---------------------------------------------------------------------------
// bf16 mma.sync GEMM (NT): C = A @ B^T (+bias+res if EPI). OutT = fp32 | bf16.
// CTA 128x128, 8 warps, warp 64x32, K-chunk 64, double-buffer, 1 barrier/iter.
// ---------------------------------------------------------------------------
#define MT 128
#define NTL 128
#define BKC 64
#define BNKT (KDIM / BKC)          // 12
#define BROWB 144
#define BSTG (256 * BROWB)
#define BGEMM_SMEM (2 * BSTG)      // 73728 B

template <bool EPI, typename OutT>
__global__ __launch_bounds__(256, 2)
void bf16_gemm(const __nv_bfloat16* __restrict__ A,
               const __nv_bfloat16* __restrict__ B,
               OutT* __restrict__ C, int M, int Ng,
               const float* __restrict__ bias, const float* __restrict__ res)
{
    extern __shared__ char smc[];
    const uint32_t sb = smem_u32(smc);

    const int tid = threadIdx.x;
    const int bm = blockIdx.x * MT;
    const int bn = blockIdx.y * NTL;

    const int w = tid >> 5, lane = tid & 31;
    const int wm = (w & 1) * 64;
    const int wn = (w >> 1) * 32;
    const int g = lane >> 2;
    const int tk = lane & 3;

    float acc[4][4][4];
#pragma unroll
    for (int i = 0; i < 4; i++)
#pragma unroll
        for (int j = 0; j < 4; j++)
#pragma unroll
            for (int q = 0; q < 4; q++) acc[i][j][q] = 0.f;

    auto load_stage = [&](int s, int kt) {
        const uint32_t Asm = sb + s * BSTG;
        const uint32_t Bsm = Asm + 128 * BROWB;
        const int k0 = kt * BKC;
#pragma unroll
        for (int c4 = 0; c4 < 4; c4++) {
            const int c = tid + c4 * 256;
            const int row = c >> 3, kq = c & 7;
            const int m = bm + row;
            const __nv_bfloat16* src =
                A + (size_t)(m < M ? m : M - 1) * KDIM + k0 + kq * 8;
            const uint32_t dst = Asm + row * BROWB + kq * 16;
            const int sz = (m < M) ? 16 : 0;
            asm volatile("cp.async.cg.shared.global [%0], [%1], 16, %2;"
                         :: "r"(dst), "l"(src), "r"(sz) : "memory");
        }
#pragma unroll
        for (int c4 = 0; c4 < 4; c4++) {
            const int c = tid + c4 * 256;
            const int row = c >> 3, kq = c & 7;
            const __nv_bfloat16* src =
                B + (size_t)(bn + row) * KDIM + k0 + kq * 8;
            const uint32_t dst = Bsm + row * BROWB + kq * 16;
            asm volatile("cp.async.cg.shared.global [%0], [%1], 16, 16;"
                         :: "r"(dst), "l"(src) : "memory");
        }
    };

    load_stage(0, 0);
    asm volatile("cp.async.commit_group;" ::: "memory");

    for (int kt = 0; kt < BNKT; kt++) {
        asm volatile("cp.async.wait_group 0;" ::: "memory");
        __syncthreads();
        // issue next-stage load first: it overlaps this iteration's compute.
        // Target buffer was consumed at iteration kt-1, guarded by the sync.
        if (kt + 1 < BNKT) load_stage((kt + 1) & 1, kt + 1);
        asm volatile("cp.async.commit_group;" ::: "memory");

        const uint32_t Asm = sb + (kt & 1) * BSTG;
        const uint32_t Bsm = Asm + 128 * BROWB;

#pragma unroll
        for (int ks = 0; ks < 4; ks++) {
            const int kb = ks * 32;
            uint32_t af[4][4], bf[4][2];
#pragma unroll
            for (int mt = 0; mt < 4; mt++) {
                const uint32_t a =
                    Asm + (wm + mt * 16 + (lane & 15)) * BROWB + (lane >> 4) * 16 + kb;
                LDSM4(af[mt], a);
            }
#pragma unroll
            for (int p = 0; p < 2; p++) {
                const int t = lane >> 3;
                const int nr = wn + (2 * p + (t >> 1)) * 8 + (lane & 7);
                const uint32_t a = Bsm + nr * BROWB + (t & 1) * 16 + kb;
                uint32_t r[4];
                LDSM4(r, a);
                bf[2 * p][0] = r[0]; bf[2 * p][1] = r[1];
                bf[2 * p + 1][0] = r[2]; bf[2 * p + 1][1] = r[3];
            }
#pragma unroll
            for (int mt = 0; mt < 4; mt++)
#pragma unroll
                for (int nt = 0; nt < 4; nt++)
                    mma_bf16(acc[mt][nt], af[mt], bf[nt][0], bf[nt][1]);
        }
    }

    // epilogue
#pragma unroll
    for (int mt = 0; mt < 4; mt++) {
#pragma unroll
        for (int half = 0; half < 2; half++) {
            const int m = bm + wm + mt * 16 + g + half * 8;
            if (m < M) {
#pragma unroll
                for (int nt = 0; nt < 4; nt++) {
                    const int n = bn + wn + nt * 8 + 2 * tk;
                    float vx = acc[mt][nt][half * 2 + 0];
                    float vy = acc[mt][nt][half * 2 + 1];
                    if (EPI) {
                        const float2 bz = *(const float2*)&bias[n];
                        const float2 rz = *(const float2*)&res[(size_t)m * Ng + n];
                        vx += bz.x + rz.x;
                        vy += bz.y + rz.y;
                    }
                    if (sizeof(OutT) == 2) {
                        *(__nv_bfloat162*)&C[(size_t)m * Ng + n] =
                            __floats2bfloat162_rn(vx, vy);
                    } else {
                        float2 v; v.x = vx; v.y = vy;
                        *(float2*)&C[(size_t)m * Ng + n] = v;
                    }
                }
            }
        }
    }
}

// ---------------------------------------------------------------------------
// bf16 mma.sync attention: one block per (b,h), 8 warps, 16 rows per warp-tile.
// Q/K/V bf16 in smem; S accum fp32; P fragments = direct cvt of S accums
// (accumulator layout == A-fragment layout, no shuffles); V via ldmatrix.trans.
// ---------------------------------------------------------------------------
#define AJP 208                 // 197 padded to 13 tiles of 16
#define AROWB 144               // 64 bf16 + 8 pad = 72 bf16 = 144 B
#define AJT 26                  // 8-wide j tiles
#define ATT_SMEM (3 * AJP * AROWB)   // 89856 B

__global__ __launch_bounds__(256)
void attn_bf16(const __nv_bfloat16* __restrict__ qkv,
               const float* __restrict__ scale,
               __nv_bfloat16* __restrict__ attout)
{
    const int bh = blockIdx.x;
    const int b = bh / HEADS;
    const int h = bh % HEADS;
    const float sc = scale[h];

    extern __shared__ char smc[];
    const uint32_t sb = smem_u32(smc);
    const uint32_t Qs = sb;
    const uint32_t Ks = sb + AJP * AROWB;
    const uint32_t Vs = sb + 2 * AJP * AROWB;

    const int tid = threadIdx.x;
    const __nv_bfloat16* base = qkv + (size_t)b * SEQ * QKV_N + h * HD;

    // stage Q, K, V (208 rows x 8 x 16B each; rows >= SEQ zero-filled)
    for (int c = tid; c < 3 * AJP * 8; c += 256) {
        const int t = c / (AJP * 8);
        const int rc = c % (AJP * 8);
        const int row = rc >> 3, ch = rc & 7;
        const __nv_bfloat16* src =
            base + (size_t)(row < SEQ ? row : SEQ - 1) * QKV_N + t * DIM + ch * 8;
        const uint32_t dst = sb + t * (AJP * AROWB) + row * AROWB + ch * 16;
        const int sz = (row < SEQ) ? 16 : 0;
        asm volatile("cp.async.cg.shared.global [%0], [%1], 16, %2;"
                     :: "r"(dst), "l"(src), "r"(sz) : "memory");
    }
    asm volatile("cp.async.commit_group;" ::: "memory");
    asm volatile("cp.async.wait_group 0;" ::: "memory");
    __syncthreads();

    const int w = tid >> 5;
    const int lane = tid & 31;
    const int g = lane >> 2;
    const int tk = lane & 3;

    for (int rb = 0; rb < 2; rb++) {
        const int rowbase = rb * 128 + w * 16;
        if (rowbase >= SEQ) continue;          // no barriers below: safe
        const int rlo = rowbase + g;
        const int rhi = rlo + 8;

        // Q A-fragments: 4 k-steps of 16
        uint32_t qa[4][4];
#pragma unroll
        for (int ks = 0; ks < 4; ks++)
            LDSM4(qa[ks], Qs + (rowbase + (lane & 15)) * AROWB
                             + (lane >> 4) * 16 + ks * 32);

        // S = Q @ K^T : 13 j-pairs x 4 k-steps
        float S[AJT][4];
#pragma unroll
        for (int nt = 0; nt < AJT; nt++)
            S[nt][0] = S[nt][1] = S[nt][2] = S[nt][3] = 0.f;
#pragma unroll
        for (int np = 0; np < 13; np++) {
#pragma unroll
            for (int ks = 0; ks < 4; ks++) {
                uint32_t r[4];
                LDSM4(r, Ks + (np * 16 + (lane & 15)) * AROWB
                            + (lane >> 4) * 16 + ks * 32);
                mma_bf16(S[2 * np],     qa[ks], r[0], r[2]);
                mma_bf16(S[2 * np + 1], qa[ks], r[1], r[3]);
            }
        }

        // scale + diagonal / out-of-range mask
#pragma unroll
        for (int nt = 0; nt < AJT; nt++) {
            const int j0 = nt * 8 + 2 * tk;
            const int j1 = j0 + 1;
            S[nt][0] = (j0 == rlo || j0 >= SEQ) ? -1e30f : S[nt][0] * sc;
            S[nt][1] = (j1 == rlo || j1 >= SEQ) ? -1e30f : S[nt][1] * sc;
            S[nt][2] = (j0 == rhi || j0 >= SEQ) ? -1e30f : S[nt][2] * sc;
            S[nt][3] = (j1 == rhi || j1 >= SEQ) ? -1e30f : S[nt][3] * sc;
        }

        // softmax (quad reductions; lanes sharing g hold the same rows)
        float mlo = -1e30f, mhi = -1e30f;
#pragma unroll
        for (int nt = 0; nt < AJT; nt++) {
            mlo = fmaxf(mlo, fmaxf(S[nt][0], S[nt][1]));
            mhi = fmaxf(mhi, fmaxf(S[nt][2], S[nt][3]));
        }
        mlo = fmaxf(mlo, __shfl_xor_sync(0xffffffffu, mlo, 1));
        mlo = fmaxf(mlo, __shfl_xor_sync(0xffffffffu, mlo, 2));
        mhi = fmaxf(mhi, __shfl_xor_sync(0xffffffffu, mhi, 1));
        mhi = fmaxf(mhi, __shfl_xor_sync(0xffffffffu, mhi, 2));

        float slo = 0.f, shi = 0.f;
#pragma unroll
        for (int nt = 0; nt < AJT; nt++) {
            S[nt][0] = __expf(S[nt][0] - mlo);
            S[nt][1] = __expf(S[nt][1] - mlo);
            S[nt][2] = __expf(S[nt][2] - mhi);
            S[nt][3] = __expf(S[nt][3] - mhi);
            slo += S[nt][0] + S[nt][1];
            shi += S[nt][2] + S[nt][3];
        }
        slo += __shfl_xor_sync(0xffffffffu, slo, 1);
        slo += __shfl_xor_sync(0xffffffffu, slo, 2);
        shi += __shfl_xor_sync(0xffffffffu, shi, 1);
        shi += __shfl_xor_sync(0xffffffffu, shi, 2);
        const float inv_lo = 1.f / slo;
        const float inv_hi = 1.f / shi;

        // P fragments: accumulator layout == A-frag layout -> direct cvt,
        // normalization folded in. No shuffles.
        uint32_t pa[13][4];
#pragma unroll
        for (int t = 0; t < 13; t++) {
            pa[t][0] = pack_bf16(S[2 * t][0] * inv_lo,     S[2 * t][1] * inv_lo);
            pa[t][1] = pack_bf16(S[2 * t][2] * inv_hi,     S[2 * t][3] * inv_hi);
            pa[t][2] = pack_bf16(S[2 * t + 1][0] * inv_lo, S[2 * t + 1][1] * inv_lo);
            pa[t][3] = pack_bf16(S[2 * t + 1][2] * inv_hi, S[2 * t + 1][3] * inv_hi);
        }

        // O = P @ V : V fragments via ldmatrix.trans on Vs[j][d]
        float O[8][4];
#pragma unroll
        for (int dt = 0; dt < 8; dt++)
            O[dt][0] = O[dt][1] = O[dt][2] = O[dt][3] = 0.f;
#pragma unroll
        for (int t = 0; t < 13; t++) {
#pragma unroll
            for (int dp = 0; dp < 4; dp++) {
                uint32_t r[4];
                LDSM4T(r, Vs + (t * 16 + (lane & 15)) * AROWB
                             + (lane >> 4) * 16 + dp * 32);
                mma_bf16(O[2 * dp],     pa[t], r[0], r[1]);
                mma_bf16(O[2 * dp + 1], pa[t], r[2], r[3]);
            }
        }

        // store (already normalized)
        __nv_bfloat16* orow_lo = attout + (size_t)(b * SEQ + rlo) * DIM + h * HD;
        __nv_bfloat16* orow_hi = attout + (size_t)(b * SEQ + rhi) * DIM + h * HD;
#pragma unroll
        for (int dt = 0; dt < 8; dt++) {
            const int d = dt * 8 + 2 * tk;
            if (rlo < SEQ)
                *(__nv_bfloat162*)&orow_lo[d] = __floats2bfloat162_rn(O[dt][0], O[dt][1]);
            if (rhi < SEQ)
                *(__nv_bfloat162*)&orow_hi[d] = __floats2bfloat162_rn(O[dt][2], O[dt][3]);
        }
    }
}

// ---------------------------------------------------------------------------
extern "C" void kernel_launch(void* const* d_in, const int* in_sizes, int n_in,
                              void* d_out, int out_size)
{
    const float* x      = (const float*)d_in[0];
    const float* scale  = (const float*)d_in[1];
    const float* w_qkv  = (const float*)d_in[2];
    const float* w_proj = (const float*)d_in[3];
    const float* b_proj = (const float*)d_in[4];
    float* out = (float*)d_out;

    __nv_bfloat16* qkvb;  cudaGetSymbolAddress((void**)&qkvb, g_qkvb);
    __nv_bfloat16* xb;    cudaGetSymbolAddress((void**)&xb, g_xb);
    __nv_bfloat16* wqb;   cudaGetSymbolAddress((void**)&wqb, g_wqb);
    __nv_bfloat16* wpb;   cudaGetSymbolAddress((void**)&wpb, g_wpb);
    __nv_bfloat16* attb;  cudaGetSymbolAddress((void**)&attb, g_attb);

    cudaFuncSetAttribute((const void*)bf16_gemm<false, __nv_bfloat16>,
                         cudaFuncAttributeMaxDynamicSharedMemorySize, BGEMM_SMEM);
    cudaFuncSetAttribute((const void*)bf16_gemm<true, float>,
                         cudaFuncAttributeMaxDynamicSharedMemorySize, BGEMM_SMEM);
    cudaFuncSetAttribute((const void*)attn_bf16,
                         cudaFuncAttributeMaxDynamicSharedMemorySize, ATT_SMEM);

    // 0) fp32 -> bf16 conversions
    {
        int n4 = (M_TOT * DIM) / 4;
        f32_to_bf16<<<(n4 + 255) / 256, 256>>>(x, xb, n4);
        n4 = (QKV_N * KDIM) / 4;
        f32_to_bf16<<<(n4 + 255) / 256, 256>>>(w_qkv, wqb, n4);
        n4 = (DIM * KDIM) / 4;
        f32_to_bf16<<<(n4 + 255) / 256, 256>>>(w_proj, wpb, n4);
    }

    // 1) qkv = x @ w_qkv^T  (bf16 in, bf16 out)
    dim3 g1((M_TOT + MT - 1) / MT, QKV_N / NTL);
    bf16_gemm<false, __nv_bfloat16><<<g1, 256, BGEMM_SMEM>>>(
        xb, wqb, qkvb, M_TOT, QKV_N, nullptr, nullptr);

    // 2) attention (bf16 mma), writes bf16
    attn_bf16<<<BATCH * HEADS, 256, ATT_SMEM>>>(qkvb, scale, attb);

    // 3) out = att @ w_proj^T + b_proj + x  (bf16 in, fp32 out + epilogue)
    dim3 g2((M_TOT + MT - 1) / MT, DIM / NTL);
    bf16_gemm<true, float><<<g2, 256, BGEMM_SMEM>>>(
        attb, wpb, out, M_TOT, DIM, b_proj, x);
}